// round 3
// baseline (speedup 1.0000x reference)
#include <cuda_runtime.h>
#include <cstdint>

#define NT   256
#define BP   128
#define STR  132            // padded SMEM row stride in words (16B-aligned rows, conflict-free)
#define OMEGA 30.0f

typedef unsigned long long ull;

// ---------------- f32x2 packed helpers (sm_100+) ----------------
__device__ __forceinline__ ull fma2(ull a, ull b, ull c) {
    ull d;
    asm("fma.rn.f32x2 %0, %1, %2, %3;" : "=l"(d) : "l"(a), "l"(b), "l"(c));
    return d;
}
__device__ __forceinline__ ull add2(ull a, ull b) {
    ull d;
    asm("add.rn.f32x2 %0, %1, %2;" : "=l"(d) : "l"(a), "l"(b));
    return d;
}
__device__ __forceinline__ ull mul2(ull a, ull b) {
    ull d;
    asm("mul.rn.f32x2 %0, %1, %2;" : "=l"(d) : "l"(a), "l"(b));
    return d;
}
__device__ __forceinline__ ull dup2(float x) {
    ull d; unsigned u = __float_as_uint(x);
    asm("mov.b64 %0, {%1, %1};" : "=l"(d) : "r"(u));
    return d;
}
__device__ __forceinline__ ull pack2(float a, float b) {
    ull d;
    asm("mov.b64 %0, {%1, %2};" : "=l"(d) : "r"(__float_as_uint(a)), "r"(__float_as_uint(b)));
    return d;
}
__device__ __forceinline__ float lo2(ull a) { return __uint_as_float((unsigned)a); }
__device__ __forceinline__ float hi2(ull a) { return __uint_as_float((unsigned)(a >> 32)); }

// ---------------- packed branchless sin(OMEGA*acc), fast-math-proof ----------------
// n = rint(x/pi) via magic-number; Cody-Waite 3-term reduction; sign = 1-2*(n mod 2)^2.
__device__ __forceinline__ ull sin2_om(ull acc) {
    const ull om     = dup2(OMEGA);
    const ull invpi  = dup2(0.318309886183790672f);
    const ull magic  = dup2(12582912.0f);     // 1.5 * 2^23
    const ull nmagic = dup2(-12582912.0f);

    ull x = mul2(acc, om);
    ull n = add2(fma2(x, invpi, magic), nmagic);         // rint(x/pi), |x/pi| << 2^22
    ull r = fma2(n, dup2(-3.140625f),             x);     // exact products
    r     = fma2(n, dup2(-9.670257568359375e-4f), r);
    r     = fma2(n, dup2(-6.27832957e-7f),        r);
    // parity sign: m = rint(n/2); par = n-2m in {-1,0,1}; sign = 1-2*par^2
    ull m   = add2(fma2(n, dup2(0.5f), magic), nmagic);
    ull par = fma2(m, dup2(-2.0f), n);
    ull sgn = fma2(mul2(par, par), dup2(-2.0f), dup2(1.0f));
    // Taylor deg-11
    ull r2 = mul2(r, r);
    ull p  = dup2(-2.50521084e-8f);
    p = fma2(p, r2, dup2( 2.75573192e-6f));
    p = fma2(p, r2, dup2(-1.98412698e-4f));
    p = fma2(p, r2, dup2( 8.33333333e-3f));
    p = fma2(p, r2, dup2(-1.66666667e-1f));
    ull s = fma2(mul2(p, r2), r, r);
    return mul2(s, sgn);
}

// ---------------- scalar accurate sincos (positional encoding only) ----------------
__device__ __forceinline__ float sin_poly(float r) {
    float r2 = r * r;
    float p = -2.50521084e-8f;
    p = fmaf(p, r2,  2.75573192e-6f);
    p = fmaf(p, r2, -1.98412698e-4f);
    p = fmaf(p, r2,  8.33333333e-3f);
    p = fmaf(p, r2, -1.66666667e-1f);
    return fmaf(p * r2, r, r);
}
__device__ __forceinline__ float cos_poly(float r) {
    float r2 = r * r;
    float p =  2.08767570e-9f;
    p = fmaf(p, r2, -2.75573192e-7f);
    p = fmaf(p, r2,  2.48015873e-5f);
    p = fmaf(p, r2, -1.38888889e-3f);
    p = fmaf(p, r2,  4.16666667e-2f);
    p = fmaf(p, r2, -0.5f);
    return fmaf(p, r2, 1.0f);
}
__device__ __forceinline__ void sincos_acc(float x, float* so, float* co) {
    float n = rintf(x * 0.318309886183790672f);
    float r = fmaf(n, -3.140625f,             x);
    r       = fmaf(n, -9.670257568359375e-4f, r);
    r       = fmaf(n, -6.27832957e-7f,        r);
    int par = ((int)n) & 1;
    float s = sin_poly(r), c = cos_poly(r);
    if (par) { s = -s; c = -c; }
    *so = s; *co = c;
}

// ---------------- 128-wide sine layer ----------------
// out[j][p] = sin(30*(sum_k in[k][p]*W[k][j] + b[j]))
// Warp covers 8 consecutive jg x 4 consecutive pg -> weight LDGs span 2 lines, act LDS 256B.
template <int K>
__device__ __forceinline__ void big_layer(const float* __restrict__ sInB, float* __restrict__ sOut,
                                          const float* __restrict__ Wg, const float* __restrict__ bg,
                                          int jg, int pg) {
    const float*  ip = sInB + (pg << 3);
    const float4* wp = (const float4*)Wg;
    const int j0 = jg << 3, p0 = pg << 3;

    ull acc[32];
#pragma unroll
    for (int jj = 0; jj < 8; jj++) {
        ull bd = dup2(__ldg(bg + j0 + jj));
#pragma unroll
        for (int pp = 0; pp < 4; pp++) acc[jj * 4 + pp] = bd;
    }

#pragma unroll 4
    for (int k = 0; k < K; k++) {
        const ulonglong2* a = (const ulonglong2*)(ip + k * STR);
        ulonglong2 q0 = a[0];
        ulonglong2 q1 = a[1];
        ull ap[4] = {q0.x, q0.y, q1.x, q1.y};
        float4 wA = __ldg(wp + k * 32 + (jg << 1));
        float4 wB = __ldg(wp + k * 32 + (jg << 1) + 1);
        ull wq[8];
        wq[0] = dup2(wA.x); wq[1] = dup2(wA.y); wq[2] = dup2(wA.z); wq[3] = dup2(wA.w);
        wq[4] = dup2(wB.x); wq[5] = dup2(wB.y); wq[6] = dup2(wB.z); wq[7] = dup2(wB.w);
#pragma unroll
        for (int jj = 0; jj < 8; jj++)
#pragma unroll
            for (int pp = 0; pp < 4; pp++)
                acc[jj * 4 + pp] = fma2(ap[pp], wq[jj], acc[jj * 4 + pp]);
    }
    __syncthreads();   // all reads of sIn done before anyone overwrites sOut (may alias sIn)

#pragma unroll
    for (int jj = 0; jj < 8; jj++) {
        float* orow = sOut + (j0 + jj) * STR + p0;
        ulonglong2 o0, o1;
        o0.x = sin2_om(acc[jj * 4 + 0]);
        o0.y = sin2_om(acc[jj * 4 + 1]);
        o1.x = sin2_om(acc[jj * 4 + 2]);
        o1.y = sin2_om(acc[jj * 4 + 3]);
        ((ulonglong2*)orow)[0] = o0;
        ((ulonglong2*)orow)[1] = o1;
    }
    __syncthreads();   // epilogue done before next layer's mainloop overwrites inputs
}

// SMEM floats: sAct 128*STR | sE 78*STR   (~106 KB -> 2 CTAs/SM)
#define SMEM_WORDS ((128 + 78) * STR)

__global__ void __launch_bounds__(NT, 2)
siren_kernel(const float* __restrict__ pts,
             const float* __restrict__ W0, const float* __restrict__ b0,
             const float* __restrict__ W1, const float* __restrict__ b1,
             const float* __restrict__ W2, const float* __restrict__ b2,
             const float* __restrict__ W3, const float* __restrict__ b3,
             const float* __restrict__ W4, const float* __restrict__ b4,
             const float* __restrict__ W5, const float* __restrict__ b5,
             const float* __restrict__ W6, const float* __restrict__ b6,
             const float* __restrict__ W7, const float* __restrict__ b7,
             float* __restrict__ out, int n) {
    extern __shared__ float sm[];
    float* sAct = sm;                    // [128][STR]
    float* sE   = sAct + 128 * STR;      // [78][STR]: rows 0..14 scalar, 15..17 x, 18..77 trig enc

    const int tid = threadIdx.x;
    const int pbase = blockIdx.x * BP;
    const int w = tid >> 5, l = tid & 31;
    const int jg = ((w & 1) << 3) | (l & 7);        // 8 consecutive jg per warp
    const int pg = ((w >> 1) << 2) | (l >> 3);      // 4 consecutive pg per warp

    // ---------------- positional encoding ----------------
    for (int idx = tid; idx < BP * 3; idx += NT) {
        int p = idx / 3, c = idx - 3 * p;
        sE[(15 + c) * STR + p] = pts[pbase * 3 + idx];
    }
    __syncthreads();
    for (int t = tid; t < BP * 30; t += NT) {
        int p = t & (BP - 1);
        int i = t >> 7;                 // 0..29
        int f = i / 3, c = i - 3 * f;
        float freq = 3.14159265358979323846f * (float)(1 << f);
        float ang = sE[(15 + c) * STR + p] * freq;
        float s, co; sincos_acc(ang, &s, &co);
        sE[(18 + 6 * f + c) * STR + p] = s;
        sE[(21 + 6 * f + c) * STR + p] = co;
    }
    __syncthreads();

    // ---------------- L0: enc(63) -> 128 ----------------
    big_layer<63>(sE + 15 * STR, sAct, W0, b0, jg, pg);
    // ---------------- L1..L3: 128 -> 128 ----------------
    big_layer<128>(sAct, sAct, W1, b1, jg, pg);
    big_layer<128>(sAct, sAct, W2, b2, jg, pg);
    big_layer<128>(sAct, sAct, W3, b3, jg, pg);

    // ---------------- L4: 128 -> 16, no activation; j0 -> density, j1..15 -> scalar ----------------
    {
        const int j = jg, pq = pg;      // 16x16 bijection reused
        const float* ip = sAct + (pq << 3);
        ull a4[4] = {0ull, 0ull, 0ull, 0ull};
#pragma unroll 4
        for (int k = 0; k < 128; k++) {
            const ulonglong2* a = (const ulonglong2*)(ip + k * STR);
            ulonglong2 q0 = a[0];
            ulonglong2 q1 = a[1];
            ull wv = dup2(__ldg(W4 + (k << 4) + j));
            a4[0] = fma2(q0.x, wv, a4[0]);
            a4[1] = fma2(q0.y, wv, a4[1]);
            a4[2] = fma2(q1.x, wv, a4[2]);
            a4[3] = fma2(q1.y, wv, a4[3]);
        }
        float bj = __ldg(b4 + j);
        if (j == 0) {
            float* od = out + n + pbase + (pq << 3);   // density block
#pragma unroll
            for (int q = 0; q < 4; q++) {
                od[2 * q]     = fmaxf(lo2(a4[q]) + bj, 0.0f);
                od[2 * q + 1] = fmaxf(hi2(a4[q]) + bj, 0.0f);
            }
        } else {
            float* orow = sE + (j - 1) * STR + (pq << 3);   // scalar features, rows 0..14
#pragma unroll
            for (int q = 0; q < 4; q++)
                *(ull*)(orow + 2 * q) = pack2(lo2(a4[q]) + bj, hi2(a4[q]) + bj);
        }
        __syncthreads();
    }

    // ---------------- L5: [scalar(15) | enc(63)] = 78 -> 128 ----------------
    big_layer<78>(sE, sAct, W5, b5, jg, pg);
    // ---------------- L6: 128 -> 128 ----------------
    big_layer<128>(sAct, sAct, W6, b6, jg, pg);

    // ---------------- L7: 128 -> 1 ----------------
    if (tid < BP) {
        float acc = 0.0f;
#pragma unroll 8
        for (int k = 0; k < 128; k++)
            acc = fmaf(sAct[k * STR + tid], __ldg(W7 + k), acc);
        out[pbase + tid] = acc + __ldg(b7);
    }
}

extern "C" void kernel_launch(void* const* d_in, const int* in_sizes, int n_in,
                              void* d_out, int out_size) {
    (void)n_in; (void)out_size;
    const float* pts = (const float*)d_in[0];
    const float* W0 = (const float*)d_in[1];  const float* b0 = (const float*)d_in[2];
    const float* W1 = (const float*)d_in[3];  const float* b1 = (const float*)d_in[4];
    const float* W2 = (const float*)d_in[5];  const float* b2 = (const float*)d_in[6];
    const float* W3 = (const float*)d_in[7];  const float* b3 = (const float*)d_in[8];
    const float* W4 = (const float*)d_in[9];  const float* b4 = (const float*)d_in[10];
    const float* W5 = (const float*)d_in[11]; const float* b5 = (const float*)d_in[12];
    const float* W6 = (const float*)d_in[13]; const float* b6 = (const float*)d_in[14];
    const float* W7 = (const float*)d_in[15]; const float* b7 = (const float*)d_in[16];
    float* out = (float*)d_out;

    int n = in_sizes[0] / 3;
    int blocks = n / BP;
    size_t shmem = (size_t)SMEM_WORDS * sizeof(float);   // ~106 KB -> 2 CTAs/SM

    cudaFuncSetAttribute(siren_kernel, cudaFuncAttributeMaxDynamicSharedMemorySize, (int)shmem);
    siren_kernel<<<blocks, NT, shmem>>>(pts, W0, b0, W1, b1, W2, b2, W3, b3,
                                        W4, b4, W5, b5, W6, b6, W7, b7, out, n);
}

// round 4
// speedup vs baseline: 1.0124x; 1.0124x over previous
#include <cuda_runtime.h>
#include <cstdint>

#define NT   256
#define BP   128
#define STR  132            // padded SMEM row stride in words (16B-aligned rows, conflict-free)
#define OMEGA 30.0f

typedef unsigned long long ull;

// ---------------- f32x2 packed-FMA helpers (sm_100+) ----------------
__device__ __forceinline__ ull fma2(ull a, ull b, ull c) {
    ull d;
    asm("fma.rn.f32x2 %0, %1, %2, %3;" : "=l"(d) : "l"(a), "l"(b), "l"(c));
    return d;
}
__device__ __forceinline__ ull dup2(float x) {
    ull d; unsigned u = __float_as_uint(x);
    asm("mov.b64 %0, {%1, %1};" : "=l"(d) : "r"(u));
    return d;
}
__device__ __forceinline__ ull pack2(float a, float b) {
    ull d;
    asm("mov.b64 %0, {%1, %2};" : "=l"(d) : "r"(__float_as_uint(a)), "r"(__float_as_uint(b)));
    return d;
}
__device__ __forceinline__ float lo2(ull a) { return __uint_as_float((unsigned)a); }
__device__ __forceinline__ float hi2(ull a) { return __uint_as_float((unsigned)(a >> 32)); }

// ---------------- accurate scalar sin/cos (immediate-constant FFMAs, fast-math-proof) ----------------
__device__ __forceinline__ float sin_poly(float r) {
    float r2 = r * r;
    float p = -2.50521084e-8f;
    p = fmaf(p, r2,  2.75573192e-6f);
    p = fmaf(p, r2, -1.98412698e-4f);
    p = fmaf(p, r2,  8.33333333e-3f);
    p = fmaf(p, r2, -1.66666667e-1f);
    return fmaf(p * r2, r, r);
}
__device__ __forceinline__ float cos_poly(float r) {
    float r2 = r * r;
    float p =  2.08767570e-9f;
    p = fmaf(p, r2, -2.75573192e-7f);
    p = fmaf(p, r2,  2.48015873e-5f);
    p = fmaf(p, r2, -1.38888889e-3f);
    p = fmaf(p, r2,  4.16666667e-2f);
    p = fmaf(p, r2, -0.5f);
    return fmaf(p, r2, 1.0f);
}
__device__ __forceinline__ float reduce_pi(float x, int* par) {
    float n = rintf(x * 0.318309886183790672f);
    float r = fmaf(n, -3.140625f,             x);
    r       = fmaf(n, -9.670257568359375e-4f, r);
    r       = fmaf(n, -6.27832957e-7f,        r);
    *par = ((int)n) & 1;
    return r;
}
__device__ __forceinline__ float sin_acc1(float x) {
    int par; float r = reduce_pi(x, &par);
    float s = sin_poly(r);
    return par ? -s : s;
}
__device__ __forceinline__ void sincos_acc(float x, float* so, float* co) {
    int par; float r = reduce_pi(x, &par);
    float s = sin_poly(r), c = cos_poly(r);
    if (par) { s = -s; c = -c; }
    *so = s; *co = c;
}

// ---------------- 128-wide sine layer ----------------
// out[j][p] = sin(30*(sum_k in[k][p]*W[k][j] + b[j]))
// Warp covers 8 consecutive jg x 4 consecutive pg:
//   weight LDG.128s span 256B contiguous (2 lines/wavefront),
//   act LDS.128s dedup to 4 distinct 16B chunks (broadcast).
template <int K>
__device__ __forceinline__ void big_layer(const float* __restrict__ sInB, float* __restrict__ sOut,
                                          const float* __restrict__ Wg, const float* __restrict__ bg,
                                          int jg, int pg) {
    const float*  ip = sInB + (pg << 3);
    const float4* wp = (const float4*)Wg;
    const int j0 = jg << 3, p0 = pg << 3;

    ull acc[32];
#pragma unroll
    for (int jj = 0; jj < 8; jj++) {
        ull bd = dup2(__ldg(bg + j0 + jj));
#pragma unroll
        for (int pp = 0; pp < 4; pp++) acc[jj * 4 + pp] = bd;
    }

#pragma unroll 4
    for (int k = 0; k < K; k++) {
        const ulonglong2* a = (const ulonglong2*)(ip + k * STR);
        ulonglong2 q0 = a[0];
        ulonglong2 q1 = a[1];
        ull ap[4] = {q0.x, q0.y, q1.x, q1.y};
        float4 wA = __ldg(wp + k * 32 + (jg << 1));
        float4 wB = __ldg(wp + k * 32 + (jg << 1) + 1);
        ull wq[8];
        wq[0] = dup2(wA.x); wq[1] = dup2(wA.y); wq[2] = dup2(wA.z); wq[3] = dup2(wA.w);
        wq[4] = dup2(wB.x); wq[5] = dup2(wB.y); wq[6] = dup2(wB.z); wq[7] = dup2(wB.w);
#pragma unroll
        for (int jj = 0; jj < 8; jj++)
#pragma unroll
            for (int pp = 0; pp < 4; pp++)
                acc[jj * 4 + pp] = fma2(ap[pp], wq[jj], acc[jj * 4 + pp]);
    }
    __syncthreads();   // all reads of sIn done before anyone overwrites sOut (may alias sIn)

#pragma unroll
    for (int jj = 0; jj < 8; jj++) {
        float* orow = sOut + (j0 + jj) * STR + p0;
        ulonglong2 o0, o1;
        o0.x = pack2(sin_acc1(OMEGA * lo2(acc[jj * 4 + 0])), sin_acc1(OMEGA * hi2(acc[jj * 4 + 0])));
        o0.y = pack2(sin_acc1(OMEGA * lo2(acc[jj * 4 + 1])), sin_acc1(OMEGA * hi2(acc[jj * 4 + 1])));
        o1.x = pack2(sin_acc1(OMEGA * lo2(acc[jj * 4 + 2])), sin_acc1(OMEGA * hi2(acc[jj * 4 + 2])));
        o1.y = pack2(sin_acc1(OMEGA * lo2(acc[jj * 4 + 3])), sin_acc1(OMEGA * hi2(acc[jj * 4 + 3])));
        ((ulonglong2*)orow)[0] = o0;
        ((ulonglong2*)orow)[1] = o1;
    }
    __syncthreads();   // epilogue done before next layer's mainloop overwrites inputs
}

// SMEM floats: sAct 128*STR | sE 78*STR   (~106 KB -> 2 CTAs/SM)
#define SMEM_WORDS ((128 + 78) * STR)

__global__ void __launch_bounds__(NT, 2)
siren_kernel(const float* __restrict__ pts,
             const float* __restrict__ W0, const float* __restrict__ b0,
             const float* __restrict__ W1, const float* __restrict__ b1,
             const float* __restrict__ W2, const float* __restrict__ b2,
             const float* __restrict__ W3, const float* __restrict__ b3,
             const float* __restrict__ W4, const float* __restrict__ b4,
             const float* __restrict__ W5, const float* __restrict__ b5,
             const float* __restrict__ W6, const float* __restrict__ b6,
             const float* __restrict__ W7, const float* __restrict__ b7,
             float* __restrict__ out, int n) {
    extern __shared__ float sm[];
    float* sAct = sm;                    // [128][STR]
    float* sE   = sAct + 128 * STR;      // [78][STR]: rows 0..14 scalar, 15..17 x, 18..77 trig enc

    const int tid = threadIdx.x;
    const int pbase = blockIdx.x * BP;
    const int w = tid >> 5, l = tid & 31;
    const int jg = ((w & 1) << 3) | (l & 7);        // 8 consecutive jg per warp
    const int pg = ((w >> 1) << 2) | (l >> 3);      // 4 consecutive pg per warp

    // ---------------- positional encoding ----------------
    for (int idx = tid; idx < BP * 3; idx += NT) {
        int p = idx / 3, c = idx - 3 * p;
        sE[(15 + c) * STR + p] = pts[pbase * 3 + idx];
    }
    __syncthreads();
    for (int t = tid; t < BP * 30; t += NT) {
        int p = t & (BP - 1);
        int i = t >> 7;                 // 0..29
        int f = i / 3, c = i - 3 * f;
        float freq = 3.14159265358979323846f * (float)(1 << f);
        float ang = sE[(15 + c) * STR + p] * freq;
        float s, co; sincos_acc(ang, &s, &co);
        sE[(18 + 6 * f + c) * STR + p] = s;
        sE[(21 + 6 * f + c) * STR + p] = co;
    }
    __syncthreads();

    // ---------------- L0: enc(63) -> 128 ----------------
    big_layer<63>(sE + 15 * STR, sAct, W0, b0, jg, pg);
    // ---------------- L1..L3: 128 -> 128 ----------------
    big_layer<128>(sAct, sAct, W1, b1, jg, pg);
    big_layer<128>(sAct, sAct, W2, b2, jg, pg);
    big_layer<128>(sAct, sAct, W3, b3, jg, pg);

    // ---------------- L4: 128 -> 16, no activation; j0 -> density, j1..15 -> scalar ----------------
    {
        const int j = jg, pq = pg;      // 16x16 bijection reused
        const float* ip = sAct + (pq << 3);
        ull a4[4];
        ull bd = dup2(__ldg(b4 + j));
#pragma unroll
        for (int q = 0; q < 4; q++) a4[q] = bd;
#pragma unroll 4
        for (int k = 0; k < 128; k++) {
            const ulonglong2* a = (const ulonglong2*)(ip + k * STR);
            ulonglong2 q0 = a[0];
            ulonglong2 q1 = a[1];
            ull wv = dup2(__ldg(W4 + (k << 4) + j));
            a4[0] = fma2(q0.x, wv, a4[0]);
            a4[1] = fma2(q0.y, wv, a4[1]);
            a4[2] = fma2(q1.x, wv, a4[2]);
            a4[3] = fma2(q1.y, wv, a4[3]);
        }
        if (j == 0) {
            float* od = out + n + pbase + (pq << 3);   // density block
#pragma unroll
            for (int q = 0; q < 4; q++) {
                od[2 * q]     = fmaxf(lo2(a4[q]), 0.0f);
                od[2 * q + 1] = fmaxf(hi2(a4[q]), 0.0f);
            }
        } else {
            float* orow = sE + (j - 1) * STR + (pq << 3);   // scalar features, rows 0..14
            ((ulonglong2*)orow)[0] = make_ulonglong2(a4[0], a4[1]);
            ((ulonglong2*)orow)[1] = make_ulonglong2(a4[2], a4[3]);
        }
        __syncthreads();
    }

    // ---------------- L5: [scalar(15) | enc(63)] = 78 -> 128 ----------------
    big_layer<78>(sE, sAct, W5, b5, jg, pg);
    // ---------------- L6: 128 -> 128 ----------------
    big_layer<128>(sAct, sAct, W6, b6, jg, pg);

    // ---------------- L7: 128 -> 1 ----------------
    if (tid < BP) {
        float acc = 0.0f;
#pragma unroll 8
        for (int k = 0; k < 128; k++)
            acc = fmaf(sAct[k * STR + tid], __ldg(W7 + k), acc);
        out[pbase + tid] = acc + __ldg(b7);
    }
}

extern "C" void kernel_launch(void* const* d_in, const int* in_sizes, int n_in,
                              void* d_out, int out_size) {
    (void)n_in; (void)out_size;
    const float* pts = (const float*)d_in[0];
    const float* W0 = (const float*)d_in[1];  const float* b0 = (const float*)d_in[2];
    const float* W1 = (const float*)d_in[3];  const float* b1 = (const float*)d_in[4];
    const float* W2 = (const float*)d_in[5];  const float* b2 = (const float*)d_in[6];
    const float* W3 = (const float*)d_in[7];  const float* b3 = (const float*)d_in[8];
    const float* W4 = (const float*)d_in[9];  const float* b4 = (const float*)d_in[10];
    const float* W5 = (const float*)d_in[11]; const float* b5 = (const float*)d_in[12];
    const float* W6 = (const float*)d_in[13]; const float* b6 = (const float*)d_in[14];
    const float* W7 = (const float*)d_in[15]; const float* b7 = (const float*)d_in[16];
    float* out = (float*)d_out;

    int n = in_sizes[0] / 3;
    int blocks = n / BP;
    size_t shmem = (size_t)SMEM_WORDS * sizeof(float);   // ~106 KB -> 2 CTAs/SM

    cudaFuncSetAttribute(siren_kernel, cudaFuncAttributeMaxDynamicSharedMemorySize, (int)shmem);
    siren_kernel<<<blocks, NT, shmem>>>(pts, W0, b0, W1, b1, W2, b2, W3, b3,
                                        W4, b4, W5, b5, W6, b6, W7, b7, out, n);
}

// round 6
// speedup vs baseline: 1.1326x; 1.1187x over previous
#include <cuda_runtime.h>
#include <cstdint>

#define NT   256
#define BP   128
#define STR  130            // padded SMEM row stride in words (8B-aligned, conflict-free)
#define OMEGA 30.0f

typedef unsigned long long ull;

// ---------------- f32x2 packed-FMA helpers (sm_100+) ----------------
__device__ __forceinline__ ull fma2(ull a, ull b, ull c) {
    ull d;
    asm("fma.rn.f32x2 %0, %1, %2, %3;" : "=l"(d) : "l"(a), "l"(b), "l"(c));
    return d;
}
__device__ __forceinline__ ull dup2(float x) {
    ull d; unsigned u = __float_as_uint(x);
    asm("mov.b64 %0, {%1, %1};" : "=l"(d) : "r"(u));
    return d;
}
__device__ __forceinline__ ull pack2(float a, float b) {
    ull d;
    asm("mov.b64 %0, {%1, %2};" : "=l"(d) : "r"(__float_as_uint(a)), "r"(__float_as_uint(b)));
    return d;
}
__device__ __forceinline__ float lo2(ull a) { return __uint_as_float((unsigned)a); }
__device__ __forceinline__ float hi2(ull a) { return __uint_as_float((unsigned)(a >> 32)); }

// ---------------- branchless sin(30*u + b30), fast-math-proof ----------------
// x = fma(u,30,b30); n = rint(x/pi) by magic-number; 3-term Cody-Waite; deg-11 Taylor;
// parity sign applied via sign-bit XOR (no branch, no FNEG).
__device__ __forceinline__ float sin_omb(float u, float b30) {
    float x  = fmaf(u, OMEGA, b30);
    float nf = fmaf(x, 0.318309886183790672f, 12582912.0f);   // 1.5*2^23 magic
    unsigned nb = __float_as_uint(nf);
    float n  = nf - 12582912.0f;                              // exact rint(x/pi)
    float r  = fmaf(n, -3.140625f,             x);
    r        = fmaf(n, -9.670257568359375e-4f, r);
    r        = fmaf(n, -6.27832957e-7f,        r);
    float r2 = r * r;
    float p  = -2.50521084e-8f;
    p = fmaf(p, r2,  2.75573192e-6f);
    p = fmaf(p, r2, -1.98412698e-4f);
    p = fmaf(p, r2,  8.33333333e-3f);
    p = fmaf(p, r2, -1.66666667e-1f);
    float s  = fmaf(p * r2, r, r);
    return __uint_as_float(__float_as_uint(s) ^ (nb << 31));  // flip sign if n odd
}

// ---------------- accurate scalar sincos (positional encoding only) ----------------
__device__ __forceinline__ float sin_poly(float r) {
    float r2 = r * r;
    float p = -2.50521084e-8f;
    p = fmaf(p, r2,  2.75573192e-6f);
    p = fmaf(p, r2, -1.98412698e-4f);
    p = fmaf(p, r2,  8.33333333e-3f);
    p = fmaf(p, r2, -1.66666667e-1f);
    return fmaf(p * r2, r, r);
}
__device__ __forceinline__ float cos_poly(float r) {
    float r2 = r * r;
    float p =  2.08767570e-9f;
    p = fmaf(p, r2, -2.75573192e-7f);
    p = fmaf(p, r2,  2.48015873e-5f);
    p = fmaf(p, r2, -1.38888889e-3f);
    p = fmaf(p, r2,  4.16666667e-2f);
    p = fmaf(p, r2, -0.5f);
    return fmaf(p, r2, 1.0f);
}
__device__ __forceinline__ void sincos_acc(float x, float* so, float* co) {
    float n = rintf(x * 0.318309886183790672f);
    float r = fmaf(n, -3.140625f,             x);
    r       = fmaf(n, -9.670257568359375e-4f, r);
    r       = fmaf(n, -6.27832957e-7f,        r);
    int par = ((int)n) & 1;
    float s = sin_poly(r), c = cos_poly(r);
    if (par) { s = -s; c = -c; }
    *so = s; *co = c;
}

// ---------------- 128-wide sine layer (R2-proven structure) ----------------
// out[j][p] = sin(30*(sum_k in[k][p]*W[k][j]) + 30*b[j])
template <int K>
__device__ __forceinline__ void big_layer(const float* __restrict__ sInB, float* __restrict__ sOut,
                                          const float* __restrict__ Wg, const float* __restrict__ bg,
                                          int jg, int pg) {
    const float*  ip = sInB + (pg << 3);
    const float4* wp = (const float4*)Wg;   // row k: quads [k*32 + jg*2], [k*32 + jg*2 + 1]
    ull acc[32];
#pragma unroll
    for (int i = 0; i < 32; i++) acc[i] = 0ull;

#pragma unroll 4
    for (int k = 0; k < K; k++) {
        const float* a = ip + k * STR;
        ull ap[4];
        ap[0] = *(const ull*)(a);
        ap[1] = *(const ull*)(a + 2);
        ap[2] = *(const ull*)(a + 4);
        ap[3] = *(const ull*)(a + 6);
        float4 wA = __ldg(wp + k * 32 + (jg << 1));
        float4 wB = __ldg(wp + k * 32 + (jg << 1) + 1);
        ull wq[8];
        wq[0] = dup2(wA.x); wq[1] = dup2(wA.y); wq[2] = dup2(wA.z); wq[3] = dup2(wA.w);
        wq[4] = dup2(wB.x); wq[5] = dup2(wB.y); wq[6] = dup2(wB.z); wq[7] = dup2(wB.w);
#pragma unroll
        for (int jj = 0; jj < 8; jj++)
#pragma unroll
            for (int pp = 0; pp < 4; pp++)
                acc[jj * 4 + pp] = fma2(ap[pp], wq[jj], acc[jj * 4 + pp]);
    }
    __syncthreads();   // all reads of sIn done before anyone overwrites sOut (may alias sIn)

    const int j0 = jg << 3, p0 = pg << 3;
#pragma unroll
    for (int jj = 0; jj < 8; jj++) {
        float b30 = OMEGA * __ldg(bg + j0 + jj);
        float* orow = sOut + (j0 + jj) * STR + p0;
#pragma unroll
        for (int pp = 0; pp < 4; pp++) {
            float v0 = sin_omb(lo2(acc[jj * 4 + pp]), b30);
            float v1 = sin_omb(hi2(acc[jj * 4 + pp]), b30);
            *(ull*)(orow + 2 * pp) = pack2(v0, v1);
        }
    }
    __syncthreads();   // epilogue done before next layer's mainloop overwrites inputs
}

// SMEM floats: sAct 128*STR | sE 78*STR   (~107 KB -> 2 CTAs/SM)
#define SMEM_WORDS ((128 + 78) * STR)

__global__ void __launch_bounds__(NT, 2)
siren_kernel(const float* __restrict__ pts,
             const float* __restrict__ W0, const float* __restrict__ b0,
             const float* __restrict__ W1, const float* __restrict__ b1,
             const float* __restrict__ W2, const float* __restrict__ b2,
             const float* __restrict__ W3, const float* __restrict__ b3,
             const float* __restrict__ W4, const float* __restrict__ b4,
             const float* __restrict__ W5, const float* __restrict__ b5,
             const float* __restrict__ W6, const float* __restrict__ b6,
             const float* __restrict__ W7, const float* __restrict__ b7,
             float* __restrict__ out, int n) {
    extern __shared__ float sm[];
    float* sAct = sm;                    // [128][STR]
    float* sE   = sAct + 128 * STR;      // [78][STR]: rows 0..14 scalar, 15..17 x, 18..77 trig enc

    const int tid = threadIdx.x;
    const int pbase = blockIdx.x * BP;
    const int jg = tid & 15, pg = tid >> 4;

    // ---------------- positional encoding ----------------
    for (int idx = tid; idx < BP * 3; idx += NT) {
        int p = idx / 3, c = idx - 3 * p;
        sE[(15 + c) * STR + p] = pts[pbase * 3 + idx];
    }
    __syncthreads();
    for (int t = tid; t < BP * 30; t += NT) {
        int p = t & (BP - 1);
        int i = t >> 7;                 // 0..29
        int f = i / 3, c = i - 3 * f;
        float freq = 3.14159265358979323846f * (float)(1 << f);
        float ang = sE[(15 + c) * STR + p] * freq;
        float s, co; sincos_acc(ang, &s, &co);
        sE[(18 + 6 * f + c) * STR + p] = s;
        sE[(21 + 6 * f + c) * STR + p] = co;
    }
    __syncthreads();

    // ---------------- L0: enc(63) -> 128 ----------------
    big_layer<63>(sE + 15 * STR, sAct, W0, b0, jg, pg);
    // ---------------- L1..L3: 128 -> 128 ----------------
    big_layer<128>(sAct, sAct, W1, b1, jg, pg);
    big_layer<128>(sAct, sAct, W2, b2, jg, pg);
    big_layer<128>(sAct, sAct, W3, b3, jg, pg);

    // ---------------- L4: 128 -> 16, no activation; j0 -> density, j1..15 -> scalar ----------------
    {
        const int j = tid & 15, pq = tid >> 4;
        const float* ip = sAct + (pq << 3);
        ull a4[4] = {0ull, 0ull, 0ull, 0ull};
#pragma unroll 4
        for (int k = 0; k < 128; k++) {
            const float* a = ip + k * STR;
            ull x0 = *(const ull*)(a);
            ull x1 = *(const ull*)(a + 2);
            ull x2 = *(const ull*)(a + 4);
            ull x3 = *(const ull*)(a + 6);
            ull w = dup2(__ldg(W4 + (k << 4) + j));
            a4[0] = fma2(x0, w, a4[0]);
            a4[1] = fma2(x1, w, a4[1]);
            a4[2] = fma2(x2, w, a4[2]);
            a4[3] = fma2(x3, w, a4[3]);
        }
        float bj = __ldg(b4 + j);
        if (j == 0) {
            float* od = out + n + pbase + (pq << 3);   // density block
#pragma unroll
            for (int q = 0; q < 4; q++) {
                od[2 * q]     = fmaxf(lo2(a4[q]) + bj, 0.0f);
                od[2 * q + 1] = fmaxf(hi2(a4[q]) + bj, 0.0f);
            }
        } else {
            float* orow = sE + (j - 1) * STR + (pq << 3);   // scalar features, rows 0..14
#pragma unroll
            for (int q = 0; q < 4; q++)
                *(ull*)(orow + 2 * q) = pack2(lo2(a4[q]) + bj, hi2(a4[q]) + bj);
        }
        __syncthreads();
    }

    // ---------------- L5: [scalar(15) | enc(63)] = 78 -> 128 ----------------
    big_layer<78>(sE, sAct, W5, b5, jg, pg);
    // ---------------- L6: 128 -> 128 ----------------
    big_layer<128>(sAct, sAct, W6, b6, jg, pg);

    // ---------------- L7: 128 -> 1 ----------------
    if (tid < BP) {
        float acc = 0.0f;
#pragma unroll 8
        for (int k = 0; k < 128; k++)
            acc = fmaf(sAct[k * STR + tid], __ldg(W7 + k), acc);
        out[pbase + tid] = acc + __ldg(b7);
    }
}

extern "C" void kernel_launch(void* const* d_in, const int* in_sizes, int n_in,
                              void* d_out, int out_size) {
    (void)n_in; (void)out_size;
    const float* pts = (const float*)d_in[0];
    const float* W0 = (const float*)d_in[1];  const float* b0 = (const float*)d_in[2];
    const float* W1 = (const float*)d_in[3];  const float* b1 = (const float*)d_in[4];
    const float* W2 = (const float*)d_in[5];  const float* b2 = (const float*)d_in[6];
    const float* W3 = (const float*)d_in[7];  const float* b3 = (const float*)d_in[8];
    const float* W4 = (const float*)d_in[9];  const float* b4 = (const float*)d_in[10];
    const float* W5 = (const float*)d_in[11]; const float* b5 = (const float*)d_in[12];
    const float* W6 = (const float*)d_in[13]; const float* b6 = (const float*)d_in[14];
    const float* W7 = (const float*)d_in[15]; const float* b7 = (const float*)d_in[16];
    float* out = (float*)d_out;

    int n = in_sizes[0] / 3;
    int blocks = n / BP;
    size_t shmem = (size_t)SMEM_WORDS * sizeof(float);   // ~107 KB -> 2 CTAs/SM

    cudaFuncSetAttribute(siren_kernel, cudaFuncAttributeMaxDynamicSharedMemorySize, (int)shmem);
    siren_kernel<<<blocks, NT, shmem>>>(pts, W0, b0, W1, b1, W2, b2, W3, b3,
                                        W4, b4, W5, b5, W6, b6, W7, b7, out, n);
}

// round 7
// speedup vs baseline: 1.1538x; 1.0187x over previous
#include <cuda_runtime.h>
#include <cstdint>

#define NT   256
#define BP   128
#define STR  130            // padded SMEM row stride in words (8B-aligned, conflict-free)
#define OMEGA 30.0f

typedef unsigned long long ull;

// ---------------- f32x2 packed-FMA helpers (sm_100+) ----------------
__device__ __forceinline__ ull fma2(ull a, ull b, ull c) {
    ull d;
    asm("fma.rn.f32x2 %0, %1, %2, %3;" : "=l"(d) : "l"(a), "l"(b), "l"(c));
    return d;
}
__device__ __forceinline__ ull dup2(float x) {
    ull d; unsigned u = __float_as_uint(x);
    asm("mov.b64 %0, {%1, %1};" : "=l"(d) : "r"(u));
    return d;
}
__device__ __forceinline__ ull pack2(float a, float b) {
    ull d;
    asm("mov.b64 %0, {%1, %2};" : "=l"(d) : "r"(__float_as_uint(a)), "r"(__float_as_uint(b)));
    return d;
}
__device__ __forceinline__ float lo2(ull a) { return __uint_as_float((unsigned)a); }
__device__ __forceinline__ float hi2(ull a) { return __uint_as_float((unsigned)(a >> 32)); }

// ---------------- branchless sin(30*u + b30), fast-math-proof ----------------
__device__ __forceinline__ float sin_omb(float u, float b30) {
    float x  = fmaf(u, OMEGA, b30);
    float nf = fmaf(x, 0.318309886183790672f, 12582912.0f);   // 1.5*2^23 magic
    unsigned nb = __float_as_uint(nf);
    float n  = nf - 12582912.0f;                              // exact rint(x/pi)
    float r  = fmaf(n, -3.140625f,             x);
    r        = fmaf(n, -9.670257568359375e-4f, r);
    r        = fmaf(n, -6.27832957e-7f,        r);
    float r2 = r * r;
    float p  = -2.50521084e-8f;
    p = fmaf(p, r2,  2.75573192e-6f);
    p = fmaf(p, r2, -1.98412698e-4f);
    p = fmaf(p, r2,  8.33333333e-3f);
    p = fmaf(p, r2, -1.66666667e-1f);
    float s  = fmaf(p * r2, r, r);
    return __uint_as_float(__float_as_uint(s) ^ (nb << 31));  // flip sign if n odd
}

// ---------------- accurate scalar sincos (positional encoding only) ----------------
__device__ __forceinline__ float sin_poly(float r) {
    float r2 = r * r;
    float p = -2.50521084e-8f;
    p = fmaf(p, r2,  2.75573192e-6f);
    p = fmaf(p, r2, -1.98412698e-4f);
    p = fmaf(p, r2,  8.33333333e-3f);
    p = fmaf(p, r2, -1.66666667e-1f);
    return fmaf(p * r2, r, r);
}
__device__ __forceinline__ float cos_poly(float r) {
    float r2 = r * r;
    float p =  2.08767570e-9f;
    p = fmaf(p, r2, -2.75573192e-7f);
    p = fmaf(p, r2,  2.48015873e-5f);
    p = fmaf(p, r2, -1.38888889e-3f);
    p = fmaf(p, r2,  4.16666667e-2f);
    p = fmaf(p, r2, -0.5f);
    return fmaf(p, r2, 1.0f);
}
__device__ __forceinline__ void sincos_acc(float x, float* so, float* co) {
    float n = rintf(x * 0.318309886183790672f);
    float r = fmaf(n, -3.140625f,             x);
    r       = fmaf(n, -9.670257568359375e-4f, r);
    r       = fmaf(n, -6.27832957e-7f,        r);
    int par = ((int)n) & 1;
    float s = sin_poly(r), c = cos_poly(r);
    if (par) { s = -s; c = -c; }
    *so = s; *co = c;
}

// ---------------- 128-wide sine layer ----------------
// out[j][p] = sin(30*(sum_k in[k][p]*W[k][j]) + 30*b[j])
// Warp covers 8 consecutive jg x 4 consecutive pg -> weight LDG.128 span 256B (2 lines),
// act LDS.64 hits 4 distinct 8B on banks {0,8,16,24} (conflict-free broadcast).
template <int K>
__device__ __forceinline__ void big_layer(const float* __restrict__ sInB, float* __restrict__ sOut,
                                          const float* __restrict__ Wg, const float* __restrict__ bg,
                                          int jg, int pg) {
    const float*  ip = sInB + (pg << 3);
    const float4* wp = (const float4*)Wg;   // row k: quads [k*32 + jg*2], [k*32 + jg*2 + 1]
    ull acc[32];
#pragma unroll
    for (int i = 0; i < 32; i++) acc[i] = 0ull;

#pragma unroll 4
    for (int k = 0; k < K; k++) {
        const float* a = ip + k * STR;
        ull ap[4];
        ap[0] = *(const ull*)(a);
        ap[1] = *(const ull*)(a + 2);
        ap[2] = *(const ull*)(a + 4);
        ap[3] = *(const ull*)(a + 6);
        float4 wA = __ldg(wp + k * 32 + (jg << 1));
        float4 wB = __ldg(wp + k * 32 + (jg << 1) + 1);
        ull wq[8];
        wq[0] = dup2(wA.x); wq[1] = dup2(wA.y); wq[2] = dup2(wA.z); wq[3] = dup2(wA.w);
        wq[4] = dup2(wB.x); wq[5] = dup2(wB.y); wq[6] = dup2(wB.z); wq[7] = dup2(wB.w);
#pragma unroll
        for (int jj = 0; jj < 8; jj++)
#pragma unroll
            for (int pp = 0; pp < 4; pp++)
                acc[jj * 4 + pp] = fma2(ap[pp], wq[jj], acc[jj * 4 + pp]);
    }
    __syncthreads();   // all reads of sIn done before anyone overwrites sOut (may alias sIn)

    const int j0 = jg << 3, p0 = pg << 3;
#pragma unroll
    for (int jj = 0; jj < 8; jj++) {
        float b30 = OMEGA * __ldg(bg + j0 + jj);
        float* orow = sOut + (j0 + jj) * STR + p0;
#pragma unroll
        for (int pp = 0; pp < 4; pp++) {
            float v0 = sin_omb(lo2(acc[jj * 4 + pp]), b30);
            float v1 = sin_omb(hi2(acc[jj * 4 + pp]), b30);
            *(ull*)(orow + 2 * pp) = pack2(v0, v1);
        }
    }
    __syncthreads();   // epilogue done before next layer's mainloop overwrites inputs
}

// SMEM floats: sAct 128*STR | sE 78*STR   (~107 KB -> 2 CTAs/SM)
#define SMEM_WORDS ((128 + 78) * STR)

__global__ void __launch_bounds__(NT, 2)
siren_kernel(const float* __restrict__ pts,
             const float* __restrict__ W0, const float* __restrict__ b0,
             const float* __restrict__ W1, const float* __restrict__ b1,
             const float* __restrict__ W2, const float* __restrict__ b2,
             const float* __restrict__ W3, const float* __restrict__ b3,
             const float* __restrict__ W4, const float* __restrict__ b4,
             const float* __restrict__ W5, const float* __restrict__ b5,
             const float* __restrict__ W6, const float* __restrict__ b6,
             const float* __restrict__ W7, const float* __restrict__ b7,
             float* __restrict__ out, int n) {
    extern __shared__ float sm[];
    float* sAct = sm;                    // [128][STR]
    float* sE   = sAct + 128 * STR;      // [78][STR]: rows 0..14 scalar, 15..17 x, 18..77 trig enc

    const int tid = threadIdx.x;
    const int pbase = blockIdx.x * BP;
    const int w = tid >> 5, l = tid & 31;
    const int jg = ((w & 1) << 3) | (l & 7);        // 8 consecutive jg per warp
    const int pg = ((w >> 1) << 2) | (l >> 3);      // 4 consecutive pg per warp

    // ---------------- positional encoding ----------------
    for (int idx = tid; idx < BP * 3; idx += NT) {
        int p = idx / 3, c = idx - 3 * p;
        sE[(15 + c) * STR + p] = pts[pbase * 3 + idx];
    }
    __syncthreads();
    for (int t = tid; t < BP * 30; t += NT) {
        int p = t & (BP - 1);
        int i = t >> 7;                 // 0..29
        int f = i / 3, c = i - 3 * f;
        float freq = 3.14159265358979323846f * (float)(1 << f);
        float ang = sE[(15 + c) * STR + p] * freq;
        float s, co; sincos_acc(ang, &s, &co);
        sE[(18 + 6 * f + c) * STR + p] = s;
        sE[(21 + 6 * f + c) * STR + p] = co;
    }
    __syncthreads();

    // ---------------- L0: enc(63) -> 128 ----------------
    big_layer<63>(sE + 15 * STR, sAct, W0, b0, jg, pg);
    // ---------------- L1..L3: 128 -> 128 ----------------
    big_layer<128>(sAct, sAct, W1, b1, jg, pg);
    big_layer<128>(sAct, sAct, W2, b2, jg, pg);
    big_layer<128>(sAct, sAct, W3, b3, jg, pg);

    // ---------------- L4: 128 -> 16, no activation; j0 -> density, j1..15 -> scalar ----------------
    {
        const int j = tid & 15, pq = tid >> 4;
        const float* ip = sAct + (pq << 3);
        ull a4[4] = {0ull, 0ull, 0ull, 0ull};
#pragma unroll 4
        for (int k = 0; k < 128; k++) {
            const float* a = ip + k * STR;
            ull x0 = *(const ull*)(a);
            ull x1 = *(const ull*)(a + 2);
            ull x2 = *(const ull*)(a + 4);
            ull x3 = *(const ull*)(a + 6);
            ull w4v = dup2(__ldg(W4 + (k << 4) + j));
            a4[0] = fma2(x0, w4v, a4[0]);
            a4[1] = fma2(x1, w4v, a4[1]);
            a4[2] = fma2(x2, w4v, a4[2]);
            a4[3] = fma2(x3, w4v, a4[3]);
        }
        float bj = __ldg(b4 + j);
        if (j == 0) {
            float* od = out + n + pbase + (pq << 3);   // density block
#pragma unroll
            for (int q = 0; q < 4; q++) {
                od[2 * q]     = fmaxf(lo2(a4[q]) + bj, 0.0f);
                od[2 * q + 1] = fmaxf(hi2(a4[q]) + bj, 0.0f);
            }
        } else {
            float* orow = sE + (j - 1) * STR + (pq << 3);   // scalar features, rows 0..14
#pragma unroll
            for (int q = 0; q < 4; q++)
                *(ull*)(orow + 2 * q) = pack2(lo2(a4[q]) + bj, hi2(a4[q]) + bj);
        }
        __syncthreads();
    }

    // ---------------- L5: [scalar(15) | enc(63)] = 78 -> 128 ----------------
    big_layer<78>(sE, sAct, W5, b5, jg, pg);
    // ---------------- L6: 128 -> 128 ----------------
    big_layer<128>(sAct, sAct, W6, b6, jg, pg);

    // ---------------- L7: 128 -> 1 ----------------
    if (tid < BP) {
        float acc = 0.0f;
#pragma unroll 8
        for (int k = 0; k < 128; k++)
            acc = fmaf(sAct[k * STR + tid], __ldg(W7 + k), acc);
        out[pbase + tid] = acc + __ldg(b7);
    }
}

extern "C" void kernel_launch(void* const* d_in, const int* in_sizes, int n_in,
                              void* d_out, int out_size) {
    (void)n_in; (void)out_size;
    const float* pts = (const float*)d_in[0];
    const float* W0 = (const float*)d_in[1];  const float* b0 = (const float*)d_in[2];
    const float* W1 = (const float*)d_in[3];  const float* b1 = (const float*)d_in[4];
    const float* W2 = (const float*)d_in[5];  const float* b2 = (const float*)d_in[6];
    const float* W3 = (const float*)d_in[7];  const float* b3 = (const float*)d_in[8];
    const float* W4 = (const float*)d_in[9];  const float* b4 = (const float*)d_in[10];
    const float* W5 = (const float*)d_in[11]; const float* b5 = (const float*)d_in[12];
    const float* W6 = (const float*)d_in[13]; const float* b6 = (const float*)d_in[14];
    const float* W7 = (const float*)d_in[15]; const float* b7 = (const float*)d_in[16];
    float* out = (float*)d_out;

    int n = in_sizes[0] / 3;
    int blocks = n / BP;
    size_t shmem = (size_t)SMEM_WORDS * sizeof(float);   // ~107 KB -> 2 CTAs/SM

    cudaFuncSetAttribute(siren_kernel, cudaFuncAttributeMaxDynamicSharedMemorySize, (int)shmem);
    siren_kernel<<<blocks, NT, shmem>>>(pts, W0, b0, W1, b1, W2, b2, W3, b3,
                                        W4, b4, W5, b5, W6, b6, W7, b7, out, n);
}